// round 15
// baseline (speedup 1.0000x reference)
#include <cuda_runtime.h>
#include <cuda_bf16.h>
#include <math.h>
#include <stdint.h>

#define TTOK 200704          // B*H*W = 64*56*56 tokens
// C=128, QKD=128, HID=512, NH=4, HD=32, WS=7, N=49, NW=64

// ---------------- scratch (device globals; no allocation allowed) ----------
__device__ __nv_bfloat16 g_xw [(size_t)TTOK * 128];   // LN2 output (bf16)
__device__ __nv_bfloat16 g_qkv[(size_t)TTOK * 384];   // qkv (windowed, bf16)
__device__ __nv_bfloat16 g_att[(size_t)TTOK * 128];   // attn out (windowed, bf16)
__device__ float         g_xres[(size_t)TTOK * 128];  // x + proj (natural, fp32)
__device__ __nv_bfloat16 g_mlp[(size_t)TTOK * 512];   // gelu(fc1) (bf16)
__device__ __nv_bfloat16 g_wq[384 * 128];
__device__ __nv_bfloat16 g_wp[128 * 128];
__device__ __nv_bfloat16 g_w1[512 * 128];
__device__ __nv_bfloat16 g_w2[128 * 512];

__device__ __forceinline__ uint32_t smem_u32(const void* p) {
    return (uint32_t)__cvta_generic_to_shared(p);
}
__device__ __forceinline__ void cp16(uint32_t dst, const void* src) {
    asm volatile("cp.async.cg.shared.global [%0], [%1], 16;" :: "r"(dst), "l"(src));
}
__device__ __forceinline__ void cp_commit() {
    asm volatile("cp.async.commit_group;" ::: "memory");
}
template <int N>
__device__ __forceinline__ void cp_wait() {
    asm volatile("cp.async.wait_group %0;" :: "n"(N) : "memory");
}
__device__ __forceinline__ void ldm_x4(uint32_t* r, uint32_t addr) {
    asm volatile("ldmatrix.sync.aligned.m8n8.x4.shared.b16 {%0,%1,%2,%3}, [%4];"
                 : "=r"(r[0]), "=r"(r[1]), "=r"(r[2]), "=r"(r[3]) : "r"(addr));
}
__device__ __forceinline__ void ldm_x4_t(uint32_t* r, uint32_t addr) {
    asm volatile("ldmatrix.sync.aligned.m8n8.x4.trans.shared.b16 {%0,%1,%2,%3}, [%4];"
                 : "=r"(r[0]), "=r"(r[1]), "=r"(r[2]), "=r"(r[3]) : "r"(addr));
}
__device__ __forceinline__ void mma16816(float* c, const uint32_t* a, const uint32_t* b) {
    asm volatile(
        "mma.sync.aligned.m16n8k16.row.col.f32.bf16.bf16.f32 "
        "{%0,%1,%2,%3}, {%4,%5,%6,%7}, {%8,%9}, {%0,%1,%2,%3};"
        : "+f"(c[0]), "+f"(c[1]), "+f"(c[2]), "+f"(c[3])
        : "r"(a[0]), "r"(a[1]), "r"(a[2]), "r"(a[3]), "r"(b[0]), "r"(b[1]));
}
__device__ __forceinline__ uint32_t packbf2(float a, float b) {
    __nv_bfloat162 h = __floats2bfloat162_rn(a, b);
    return *(uint32_t*)&h;
}

// ---------------- fp32 -> bf16 weight conversion (all 4 in one launch) -----
__global__ void f2bf_all(const float* __restrict__ s0, __nv_bfloat16* __restrict__ d0, int n0,
                         const float* __restrict__ s1, __nv_bfloat16* __restrict__ d1, int n1,
                         const float* __restrict__ s2, __nv_bfloat16* __restrict__ d2, int n2,
                         const float* __restrict__ s3, __nv_bfloat16* __restrict__ d3, int n3) {
    int i = (blockIdx.x * blockDim.x + threadIdx.x) * 4;
    const float* s; __nv_bfloat16* d;
    if (i < n0) { s = s0 + i; d = d0 + i; }
    else if ((i -= n0) < n1) { s = s1 + i; d = d1 + i; }
    else if ((i -= n1) < n2) { s = s2 + i; d = d2 + i; }
    else if ((i -= n2) < n3) { s = s3 + i; d = d3 + i; }
    else return;
    float4 v = *(const float4*)s;
    __nv_bfloat162* dp = (__nv_bfloat162*)d;
    dp[0] = __floats2bfloat162_rn(v.x, v.y);
    dp[1] = __floats2bfloat162_rn(v.z, v.w);
}

// natural-order output row -> windowed-order attention row
__device__ __forceinline__ size_t proj_gather(size_t m) {
    int bb = (int)(m / 3136);
    int r  = (int)(m - (size_t)bb * 3136);
    int h = r / 56, w = r - h * 56;
    int gh = h + 53; if (gh >= 56) gh -= 56;
    int gw = w + 53; if (gw >= 56) gw -= 56;
    int win = bb * 64 + (gh / 7) * 8 + (gw / 7);
    int n = (gh % 7) * 7 + (gw % 7);
    return (size_t)win * 49 + n;
}

// ---------------- full-K bf16 HMMA GEMM (K=128) ----------------------------
// C[M,N] = A[M,128] @ W[N,128]^T. BM=BN=128, whole K staged once, single sync.
// AMODE: 0 = A bf16 direct; 1 = A bf16 + proj_gather rows;
//        2 = A fp32 + LN1 + shift/window gather (computed in the load).
// EPI:   0 = bias -> bf16 ; 1 = bias + exact GELU -> bf16 ;
//        2 = bias + residual -> fp32 xres, then LN2 -> bf16 xw (N must be 128)
#define FSTR 136
#define FULLK_SMEM (2 * 128 * FSTR * 2)

template <int AMODE, int EPI>
__global__ void __launch_bounds__(256, 2)
fgemm(const void* __restrict__ Ain, const __nv_bfloat16* __restrict__ W,
      const float* __restrict__ bias, const float* __restrict__ res,
      const float* __restrict__ ln_g, const float* __restrict__ ln_b,
      void* __restrict__ Cout, __nv_bfloat16* __restrict__ xwout, int M, int N) {
    extern __shared__ __nv_bfloat16 sh[];
    __nv_bfloat16* As = sh;
    __nv_bfloat16* Bs = sh + 128 * FSTR;
    int t = threadIdx.x;
    int wid = t >> 5, lane = t & 31;
    int bm = blockIdx.y << 7, bn = blockIdx.x << 7;
    int wm = (wid & 3) * 32, wn = (wid >> 2) * 64;
    int lrow = t >> 1, half = t & 1;

    // --- B tile: cp.async, 8x16B per thread
    {
        const __nv_bfloat16* Wp = W + (size_t)(bn + lrow) * 128 + half * 64;
        uint32_t sB = smem_u32(Bs + lrow * FSTR + half * 64);
#pragma unroll
        for (int i = 0; i < 8; i++) cp16(sB + i * 16, Wp + i * 8);
    }

    // --- A tile
    if (AMODE == 2) {
        // LN1 + roll(-3,-3) + window-partition gather, fp32 -> bf16
        int tok = bm + lrow;
        int win = tok / 49, n = tok - win * 49;
        int bb = win >> 6, wrem = win & 63;
        int ny = n / 7, nx = n - ny * 7;
        int gh = (wrem >> 3) * 7 + ny;
        int gw = (wrem & 7) * 7 + nx;
        int shh = gh + 3; if (shh >= 56) shh -= 56;
        int sww = gw + 3; if (sww >= 56) sww -= 56;
        const float* xr = (const float*)Ain +
            ((size_t)bb * 3136 + shh * 56 + sww) * 128 + half * 64;
        float s = 0.0f, q = 0.0f;
#pragma unroll
        for (int i = 0; i < 16; i++) {
            float4 v = __ldg((const float4*)(xr + i * 4));
            s += v.x + v.y + v.z + v.w;
            q += v.x * v.x + v.y * v.y + v.z * v.z + v.w * v.w;
        }
        s += __shfl_xor_sync(0xffffffffu, s, 1);
        q += __shfl_xor_sync(0xffffffffu, q, 1);
        float mu = s * (1.0f / 128.0f);
        float inv = rsqrtf(q * (1.0f / 128.0f) - mu * mu + 1e-5f);
        __nv_bfloat16* dst = As + lrow * FSTR + half * 64;
#pragma unroll
        for (int i = 0; i < 8; i++) {
            float4 v0 = __ldg((const float4*)(xr + i * 8));
            float4 v1 = __ldg((const float4*)(xr + i * 8 + 4));
            float4 g0 = __ldg((const float4*)(ln_g + half * 64 + i * 8));
            float4 g1 = __ldg((const float4*)(ln_g + half * 64 + i * 8 + 4));
            float4 b0 = __ldg((const float4*)(ln_b + half * 64 + i * 8));
            float4 b1 = __ldg((const float4*)(ln_b + half * 64 + i * 8 + 4));
            __nv_bfloat162 h[4];
            h[0] = __floats2bfloat162_rn((v0.x - mu) * inv * g0.x + b0.x,
                                         (v0.y - mu) * inv * g0.y + b0.y);
            h[1] = __floats2bfloat162_rn((v0.z - mu) * inv * g0.z + b0.z,
                                         (v0.w - mu) * inv * g0.w + b0.w);
            h[2] = __floats2bfloat162_rn((v1.x - mu) * inv * g1.x + b1.x,
                                         (v1.y - mu) * inv * g1.y + b1.y);
            h[3] = __floats2bfloat162_rn((v1.z - mu) * inv * g1.z + b1.z,
                                         (v1.w - mu) * inv * g1.w + b1.w);
            *(uint4*)(dst + i * 8) = *(uint4*)h;
        }
    } else {
        size_t ar = (size_t)(bm + lrow);
        if (AMODE == 1) ar = proj_gather(ar);
        const __nv_bfloat16* Ap = (const __nv_bfloat16*)Ain + ar * 128 + half * 64;
        uint32_t sA = smem_u32(As + lrow * FSTR + half * 64);
#pragma unroll
        for (int i = 0; i < 8; i++) cp16(sA + i * 16, Ap + i * 8);
    }
    cp_commit();
    cp_wait<0>();
    __syncthreads();

    // --- MMA: 8 uninterrupted k16 steps
    float acc[2][8][4];
#pragma unroll
    for (int i = 0; i < 2; i++)
#pragma unroll
        for (int j = 0; j < 8; j++)
#pragma unroll
            for (int q = 0; q < 4; q++) acc[i][j][q] = 0.0f;

    uint32_t a_addr0 = smem_u32(&As[(wm + (lane & 15)) * FSTR + ((lane >> 4) << 3)]);
    uint32_t b_addr0 = smem_u32(&Bs[(wn + (lane & 7) + ((lane >> 4) << 3)) * FSTR +
                                    (((lane >> 3) & 1) << 3)]);
#pragma unroll
    for (int kk = 0; kk < 8; kk++) {
        uint32_t af[2][4];
#pragma unroll
        for (int mt = 0; mt < 2; mt++)
            ldm_x4(af[mt], a_addr0 + (mt * 16 * FSTR + kk * 16) * 2);
        uint32_t bfr[4][4];
#pragma unroll
        for (int bt = 0; bt < 4; bt++)
            ldm_x4(bfr[bt], b_addr0 + (bt * 16 * FSTR + kk * 16) * 2);
#pragma unroll
        for (int mt = 0; mt < 2; mt++)
#pragma unroll
            for (int nt = 0; nt < 8; nt++)
                mma16816(acc[mt][nt], af[mt], &bfr[nt >> 1][(nt & 1) * 2]);
    }

    // --- epilogue
    int r0 = lane >> 2;
    int c0 = (lane & 3) * 2;
    if (EPI != 2) {
#pragma unroll
        for (int mt = 0; mt < 2; mt++)
#pragma unroll
            for (int hf = 0; hf < 2; hf++) {
                int row = bm + wm + mt * 16 + r0 + hf * 8;
#pragma unroll
                for (int nt = 0; nt < 8; nt++) {
                    int col = bn + wn + nt * 8 + c0;
                    float v0 = acc[mt][nt][hf * 2 + 0] + bias[col];
                    float v1 = acc[mt][nt][hf * 2 + 1] + bias[col + 1];
                    if (EPI == 1) {
                        v0 = 0.5f * v0 * (1.0f + erff(v0 * 0.70710678118654752f));
                        v1 = 0.5f * v1 * (1.0f + erff(v1 * 0.70710678118654752f));
                    }
                    *(__nv_bfloat162*)((__nv_bfloat16*)Cout + (size_t)row * N + col) =
                        __floats2bfloat162_rn(v0, v1);
                }
            }
    } else {
        // bias + residual -> fp32 xres, accumulate row stats
        float rsum[2][2], rsq[2][2];
#pragma unroll
        for (int mt = 0; mt < 2; mt++)
#pragma unroll
            for (int hf = 0; hf < 2; hf++) {
                rsum[mt][hf] = 0.0f; rsq[mt][hf] = 0.0f;
                int row = bm + wm + mt * 16 + r0 + hf * 8;
                float* xr = (float*)Cout + (size_t)row * 128;
                const float* rr = res + (size_t)row * 128;
#pragma unroll
                for (int nt = 0; nt < 8; nt++) {
                    int col = wn + nt * 8 + c0;
                    float2 rv = *(const float2*)(rr + col);
                    float v0 = acc[mt][nt][hf * 2 + 0] + bias[col] + rv.x;
                    float v1 = acc[mt][nt][hf * 2 + 1] + bias[col + 1] + rv.y;
                    *(float2*)(xr + col) = make_float2(v0, v1);
                    rsum[mt][hf] += v0 + v1;
                    rsq[mt][hf] += v0 * v0 + v1 * v1;
                }
                rsum[mt][hf] += __shfl_xor_sync(0xffffffffu, rsum[mt][hf], 1);
                rsq[mt][hf]  += __shfl_xor_sync(0xffffffffu, rsq[mt][hf], 1);
                rsum[mt][hf] += __shfl_xor_sync(0xffffffffu, rsum[mt][hf], 2);
                rsq[mt][hf]  += __shfl_xor_sync(0xffffffffu, rsq[mt][hf], 2);
            }
        __syncthreads();                 // As no longer needed -> scratch
        float2* scr = (float2*)As;       // [128][2] (sum, sumsq)
        if ((lane & 3) == 0) {
#pragma unroll
            for (int mt = 0; mt < 2; mt++)
#pragma unroll
                for (int hf = 0; hf < 2; hf++) {
                    int rl = wm + mt * 16 + r0 + hf * 8;
                    scr[rl * 2 + (wid >> 2)] = make_float2(rsum[mt][hf], rsq[mt][hf]);
                }
        }
        __syncthreads();
        // pass 2: normalize (re-read own xres writes), emit bf16 xw
#pragma unroll
        for (int mt = 0; mt < 2; mt++)
#pragma unroll
            for (int hf = 0; hf < 2; hf++) {
                int rl = wm + mt * 16 + r0 + hf * 8;
                float2 s0 = scr[rl * 2], s1 = scr[rl * 2 + 1];
                float mu = (s0.x + s1.x) * (1.0f / 128.0f);
                float inv = rsqrtf((s0.y + s1.y) * (1.0f / 128.0f) - mu * mu + 1e-5f);
                int row = bm + rl;
                const float* xr = (const float*)Cout + (size_t)row * 128;
                __nv_bfloat16* xo = xwout + (size_t)row * 128;
#pragma unroll
                for (int nt = 0; nt < 8; nt++) {
                    int col = wn + nt * 8 + c0;
                    float2 v = *(const float2*)(xr + col);
                    float2 g = *(const float2*)(ln_g + col);
                    float2 b = *(const float2*)(ln_b + col);
                    *(__nv_bfloat162*)(xo + col) = __floats2bfloat162_rn(
                        (v.x - mu) * inv * g.x + b.x, (v.y - mu) * inv * g.y + b.y);
                }
            }
    }
}

// ---------------- pipelined hgemm (used for fc2, K=512) --------------------
#define SSTR 40

__global__ void __launch_bounds__(256, 2)
hgemm_res(const __nv_bfloat16* __restrict__ A, const __nv_bfloat16* __restrict__ W,
          const float* __restrict__ bias, const float* __restrict__ res,
          float* __restrict__ Cout, int M, int N, int K) {
    __shared__ __nv_bfloat16 As[2][128 * SSTR];
    __shared__ __nv_bfloat16 Bs[2][128 * SSTR];
    int t = threadIdx.x;
    int wid = t >> 5, lane = t & 31;
    int bm = blockIdx.y << 7, bn = blockIdx.x << 7;
    int wm = (wid & 3) * 32;
    int wn = (wid >> 2) * 64;

    int lrow = t >> 1;
    int half = t & 1;
    const __nv_bfloat16* Ap = A + (size_t)(bm + lrow) * K + half * 16;
    const __nv_bfloat16* Wp = W + (size_t)(bn + lrow) * K + half * 16;
    uint32_t sA = smem_u32(&As[0][0]) + lrow * (SSTR * 2) + half * 32;
    uint32_t sB = smem_u32(&Bs[0][0]) + lrow * (SSTR * 2) + half * 32;
    const uint32_t STG = 128 * SSTR * 2;

    int nk = K >> 5;
    {
        cp16(sA, Ap); cp16(sA + 16, Ap + 8);
        cp16(sB, Wp); cp16(sB + 16, Wp + 8);
        cp_commit();
        cp16(sA + STG, Ap + 32); cp16(sA + STG + 16, Ap + 40);
        cp16(sB + STG, Wp + 32); cp16(sB + STG + 16, Wp + 40);
        cp_commit();
    }

    float acc[2][8][4];
#pragma unroll
    for (int i = 0; i < 2; i++)
#pragma unroll
        for (int j = 0; j < 8; j++)
#pragma unroll
            for (int q = 0; q < 4; q++) acc[i][j][q] = 0.0f;

    uint32_t a_addr0 = smem_u32(&As[0][(wm + (lane & 15)) * SSTR + ((lane >> 4) << 3)]);
    uint32_t b_addr0 = smem_u32(&Bs[0][(wn + (lane & 7) + ((lane >> 4) << 3)) * SSTR +
                                       (((lane >> 3) & 1) << 3)]);

    for (int c = 0; c < nk; c++) {
        if (c + 1 < nk) cp_wait<1>(); else cp_wait<0>();
        __syncthreads();
        uint32_t soff = (c & 1) * STG;
#pragma unroll
        for (int kk = 0; kk < 2; kk++) {
            uint32_t af[2][4];
#pragma unroll
            for (int mt = 0; mt < 2; mt++)
                ldm_x4(af[mt], a_addr0 + soff + (mt * 16 * SSTR + kk * 16) * 2);
            uint32_t bfr[4][4];
#pragma unroll
            for (int bt = 0; bt < 4; bt++)
                ldm_x4(bfr[bt], b_addr0 + soff + (bt * 16 * SSTR + kk * 16) * 2);
#pragma unroll
            for (int mt = 0; mt < 2; mt++)
#pragma unroll
                for (int nt = 0; nt < 8; nt++)
                    mma16816(acc[mt][nt], af[mt], &bfr[nt >> 1][(nt & 1) * 2]);
        }
        if (c + 2 < nk) {
            __syncthreads();
            const __nv_bfloat16* ap = Ap + (c + 2) * 32;
            const __nv_bfloat16* wp = Wp + (c + 2) * 32;
            cp16(sA + soff, ap); cp16(sA + soff + 16, ap + 8);
            cp16(sB + soff, wp); cp16(sB + soff + 16, wp + 8);
            cp_commit();
        }
    }

    int r0 = lane >> 2;
    int c0 = (lane & 3) * 2;
#pragma unroll
    for (int mt = 0; mt < 2; mt++)
#pragma unroll
        for (int hf = 0; hf < 2; hf++) {
            int row = bm + wm + mt * 16 + r0 + hf * 8;
#pragma unroll
            for (int nt = 0; nt < 8; nt++) {
                int col = bn + wn + nt * 8 + c0;
                float v0 = acc[mt][nt][hf * 2 + 0] + bias[col];
                float v1 = acc[mt][nt][hf * 2 + 1] + bias[col + 1];
                const float2 rv = *(const float2*)(res + (size_t)row * N + col);
                *(float2*)(Cout + (size_t)row * N + col) =
                    make_float2(v0 + rv.x, v1 + rv.y);
            }
        }
}

// ---------------- Windowed attention: HMMA, one block per window -----------
#define ASTR 136
#define ATTN_SMEM (192 * ASTR * 2 + 676 * 4 + 64 * 4)

__global__ void __launch_bounds__(256)
attn_kernel(const __nv_bfloat16* __restrict__ qkv, const float* __restrict__ rpb,
            __nv_bfloat16* __restrict__ out) {
    extern __shared__ __nv_bfloat16 sm[];
    __nv_bfloat16* qs  = sm;
    __nv_bfloat16* ksm = sm + 64 * ASTR;
    __nv_bfloat16* vsm = sm + 128 * ASTR;
    float* rps4 = (float*)(sm + 192 * ASTR);
    int* regid  = (int*)(rps4 + 676);

    int win = blockIdx.x;
    int t = threadIdx.x;
    int lane = t & 31, wid = t >> 5;
    int head = wid >> 1;
    int ms = (wid & 1) * 32;

    int wrem = win & 63;
    int wh = wrem >> 3, ww = wrem & 7;
    if (t < 49) {
        int y = (t * 2341) >> 14, xx = t - y * 7;
        int gh = wh * 7 + y, gw = ww * 7 + xx;
        int rh = gh < 49 ? 0 : (gh < 53 ? 1 : 2);
        int rw = gw < 49 ? 0 : (gw < 53 ? 1 : 2);
        regid[t] = rh * 3 + rw;
    }
    for (int i = t; i < 676; i += 256) {
        int h = i / 169, r = i - h * 169;
        rps4[h * 169 + r] = rpb[r * 4 + h];
    }
    size_t base = (size_t)win * 49 * 384;
    for (int idx = t; idx < 2352; idx += 256) {
        int nn = idx / 48, c = idx - nn * 48;
        uint4 v = *(const uint4*)(qkv + base + nn * 384 + c * 8);
        int sec = c >> 4, col = (c & 15) * 8;
        __nv_bfloat16* dst = (sec == 0) ? qs : (sec == 1) ? ksm : vsm;
        *(uint4*)&dst[nn * ASTR + col] = v;
    }
    uint4 z = make_uint4(0, 0, 0, 0);
    for (int idx = t; idx < 720; idx += 256) {
        int pr = idx / 48, c = idx - pr * 48;
        int rr = 49 + pr;
        int sec = c >> 4, col = (c & 15) * 8;
        __nv_bfloat16* dst = (sec == 0) ? qs : (sec == 1) ? ksm : vsm;
        *(uint4*)&dst[rr * ASTR + col] = z;
    }
    __syncthreads();

    float sc[2][7][4];
#pragma unroll
    for (int i = 0; i < 2; i++)
#pragma unroll
        for (int j = 0; j < 7; j++)
#pragma unroll
            for (int q = 0; q < 4; q++) sc[i][j][q] = 0.0f;

    uint32_t a_base = smem_u32(&qs[(ms + (lane & 15)) * ASTR + head * 32 + ((lane >> 4) << 3)]);
    uint32_t b_base = smem_u32(&ksm[((lane & 7) + ((lane >> 4) << 3)) * ASTR + head * 32 +
                                    (((lane >> 3) & 1) << 3)]);
#pragma unroll
    for (int kk = 0; kk < 2; kk++) {
        uint32_t af[2][4];
#pragma unroll
        for (int mt = 0; mt < 2; mt++)
            ldm_x4(af[mt], a_base + (mt * 16 * ASTR + kk * 16) * 2);
        uint32_t bfr[4][4];
#pragma unroll
        for (int bt = 0; bt < 4; bt++)
            ldm_x4(bfr[bt], b_base + (bt * 16 * ASTR + kk * 16) * 2);
#pragma unroll
        for (int mt = 0; mt < 2; mt++)
#pragma unroll
            for (int nt = 0; nt < 7; nt++)
                mma16816(sc[mt][nt], af[mt], &bfr[nt >> 1][(nt & 1) * 2]);
    }

    const float SCALE = 0.17677669529663687f;
    int rY[2][2], rX[2][2], rR[2][2]; bool rV[2][2];
#pragma unroll
    for (int mt = 0; mt < 2; mt++)
#pragma unroll
        for (int rh = 0; rh < 2; rh++) {
            int r = ms + mt * 16 + (lane >> 2) + rh * 8;
            bool v = r < 49;
            rV[mt][rh] = v;
            int rc = v ? r : 0;
            rY[mt][rh] = (rc * 2341) >> 14;
            rX[mt][rh] = rc - rY[mt][rh] * 7;
            rR[mt][rh] = regid[rc];
        }
#pragma unroll
    for (int nt = 0; nt < 7; nt++) {
#pragma unroll
        for (int e = 0; e < 2; e++) {
            int m = nt * 8 + (lane & 3) * 2 + e;
            bool mv = m < 49;
            int mc = mv ? m : 0;
            int y2 = (mc * 2341) >> 14, x2 = mc - y2 * 7;
            int rm = regid[mc];
#pragma unroll
            for (int mt = 0; mt < 2; mt++)
#pragma unroll
                for (int rh = 0; rh < 2; rh++) {
                    float s = sc[mt][nt][rh * 2 + e] * SCALE;
                    if (mv && rV[mt][rh]) {
                        s += rps4[head * 169 + (rY[mt][rh] - y2 + 6) * 13 +
                                  (rX[mt][rh] - x2 + 6)];
                        if (rR[mt][rh] != rm) s -= 100.0f;
                    } else {
                        s = -1e30f;
                    }
                    sc[mt][nt][rh * 2 + e] = s;
                }
        }
    }

    float rinv[2][2];
#pragma unroll
    for (int mt = 0; mt < 2; mt++)
#pragma unroll
        for (int rh = 0; rh < 2; rh++) {
            float mx = -1e30f;
#pragma unroll
            for (int nt = 0; nt < 7; nt++)
                mx = fmaxf(mx, fmaxf(sc[mt][nt][rh * 2], sc[mt][nt][rh * 2 + 1]));
            mx = fmaxf(mx, __shfl_xor_sync(0xffffffffu, mx, 1));
            mx = fmaxf(mx, __shfl_xor_sync(0xffffffffu, mx, 2));
            float sum = 0.0f;
#pragma unroll
            for (int nt = 0; nt < 7; nt++) {
                float e0 = __expf(sc[mt][nt][rh * 2] - mx);
                float e1 = __expf(sc[mt][nt][rh * 2 + 1] - mx);
                sc[mt][nt][rh * 2] = e0;
                sc[mt][nt][rh * 2 + 1] = e1;
                sum += e0 + e1;
            }
            sum += __shfl_xor_sync(0xffffffffu, sum, 1);
            sum += __shfl_xor_sync(0xffffffffu, sum, 2);
            rinv[mt][rh] = rV[mt][rh] ? (1.0f / sum) : 0.0f;
        }

    float oc[2][4][4];
#pragma unroll
    for (int i = 0; i < 2; i++)
#pragma unroll
        for (int j = 0; j < 4; j++)
#pragma unroll
            for (int q = 0; q < 4; q++) oc[i][j][q] = 0.0f;

    uint32_t vb = smem_u32(&vsm[(lane & 15) * ASTR + head * 32 + ((lane >> 4) << 3)]);
#pragma unroll
    for (int ks = 0; ks < 4; ks++) {
        uint32_t bv[2][4];
        ldm_x4_t(bv[0], vb + (ks * 16 * ASTR) * 2);
        ldm_x4_t(bv[1], vb + (ks * 16 * ASTR + 16) * 2);
#pragma unroll
        for (int mt = 0; mt < 2; mt++) {
            float il = rinv[mt][0], ih = rinv[mt][1];
            int n0 = 2 * ks, n1 = 2 * ks + 1;
            uint32_t a[4];
            a[0] = packbf2(sc[mt][n0][0] * il, sc[mt][n0][1] * il);
            a[1] = packbf2(sc[mt][n0][2] * ih, sc[mt][n0][3] * ih);
            if (n1 < 7) {
                a[2] = packbf2(sc[mt][n1][0] * il, sc[mt][n1][1] * il);
                a[3] = packbf2(sc[mt][n1][2] * ih, sc[mt][n1][3] * ih);
            } else {
                a[2] = 0u; a[3] = 0u;
            }
#pragma unroll
            for (int dt = 0; dt < 4; dt++)
                mma16816(oc[mt][dt], a, &bv[dt >> 1][(dt & 1) * 2]);
        }
    }

    size_t ob = (size_t)win * 49 * 128 + head * 32;
#pragma unroll
    for (int mt = 0; mt < 2; mt++)
#pragma unroll
        for (int rh = 0; rh < 2; rh++) {
            int r = ms + mt * 16 + (lane >> 2) + rh * 8;
            if (r < 49) {
#pragma unroll
                for (int dt = 0; dt < 4; dt++) {
                    int d = dt * 8 + (lane & 3) * 2;
                    __nv_bfloat162 o2 = __floats2bfloat162_rn(oc[mt][dt][rh * 2],
                                                              oc[mt][dt][rh * 2 + 1]);
                    *(__nv_bfloat162*)(out + ob + (size_t)r * 128 + d) = o2;
                }
            }
        }
}

// ---------------- launch ---------------------------------------------------
extern "C" void kernel_launch(void* const* d_in, const int* in_sizes, int n_in,
                              void* d_out, int out_size) {
    const float* x      = (const float*)d_in[0];
    const float* ln1_g  = (const float*)d_in[1];
    const float* ln1_b  = (const float*)d_in[2];
    const float* qkv_w  = (const float*)d_in[3];
    const float* qkv_b  = (const float*)d_in[4];
    const float* rpb    = (const float*)d_in[5];
    const float* proj_w = (const float*)d_in[6];
    const float* proj_b = (const float*)d_in[7];
    const float* ln2_g  = (const float*)d_in[8];
    const float* ln2_b  = (const float*)d_in[9];
    const float* fc1_w  = (const float*)d_in[10];
    const float* fc1_b  = (const float*)d_in[11];
    const float* fc2_w  = (const float*)d_in[12];
    const float* fc2_b  = (const float*)d_in[13];
    float* out = (float*)d_out;

    void* p;
    cudaGetSymbolAddress(&p, g_xw);   __nv_bfloat16* xw   = (__nv_bfloat16*)p;
    cudaGetSymbolAddress(&p, g_qkv);  __nv_bfloat16* qkvb = (__nv_bfloat16*)p;
    cudaGetSymbolAddress(&p, g_att);  __nv_bfloat16* att  = (__nv_bfloat16*)p;
    cudaGetSymbolAddress(&p, g_xres); float*         xres = (float*)p;
    cudaGetSymbolAddress(&p, g_mlp);  __nv_bfloat16* mlp  = (__nv_bfloat16*)p;
    cudaGetSymbolAddress(&p, g_wq);   __nv_bfloat16* wq = (__nv_bfloat16*)p;
    cudaGetSymbolAddress(&p, g_wp);   __nv_bfloat16* wp = (__nv_bfloat16*)p;
    cudaGetSymbolAddress(&p, g_w1);   __nv_bfloat16* w1 = (__nv_bfloat16*)p;
    cudaGetSymbolAddress(&p, g_w2);   __nv_bfloat16* w2 = (__nv_bfloat16*)p;

    cudaFuncSetAttribute(attn_kernel, cudaFuncAttributeMaxDynamicSharedMemorySize, ATTN_SMEM);
    cudaFuncSetAttribute(fgemm<2, 0>, cudaFuncAttributeMaxDynamicSharedMemorySize, FULLK_SMEM);
    cudaFuncSetAttribute(fgemm<1, 2>, cudaFuncAttributeMaxDynamicSharedMemorySize, FULLK_SMEM);
    cudaFuncSetAttribute(fgemm<0, 1>, cudaFuncAttributeMaxDynamicSharedMemorySize, FULLK_SMEM);

    // weight conversion (bf16), single launch
    f2bf_all<<<192, 256>>>(qkv_w, wq, 384 * 128, proj_w, wp, 128 * 128,
                           fc1_w, w1, 512 * 128, fc2_w, w2, 128 * 512);

    // 1. QKV projection with fused LN1 + shift/window gather
    fgemm<2, 0><<<dim3(3, 1568), 256, FULLK_SMEM>>>(
        x, wq, qkv_b, nullptr, ln1_g, ln1_b, qkvb, nullptr, TTOK, 384);
    // 2. Windowed attention
    attn_kernel<<<4096, 256, ATTN_SMEM>>>(qkvb, rpb, att);
    // 3. proj + window-reverse gather + residual -> xres, fused LN2 -> xw
    fgemm<1, 2><<<dim3(1, 1568), 256, FULLK_SMEM>>>(
        att, wp, proj_b, x, ln2_g, ln2_b, xres, xw, TTOK, 128);
    // 4. fc1 + exact GELU
    fgemm<0, 1><<<dim3(4, 1568), 256, FULLK_SMEM>>>(
        xw, w1, fc1_b, nullptr, nullptr, nullptr, mlp, nullptr, TTOK, 512);
    // 5. fc2 + residual -> output (fp32)
    hgemm_res<<<dim3(1, 1568), 256>>>(mlp, w2, fc2_b, xres, out, TTOK, 128, 512);
}

// round 16
// speedup vs baseline: 1.1602x; 1.1602x over previous
#include <cuda_runtime.h>
#include <cuda_bf16.h>
#include <math.h>
#include <stdint.h>

#define TTOK 200704          // B*H*W = 64*56*56 tokens
// C=128, QKD=128, HID=512, NH=4, HD=32, WS=7, N=49, NW=64

// ---------------- scratch (device globals; no allocation allowed) ----------
__device__ __nv_bfloat16 g_xw [(size_t)TTOK * 128];   // LN output (bf16)
__device__ __nv_bfloat16 g_qkv[(size_t)TTOK * 384];   // qkv (windowed, bf16)
__device__ __nv_bfloat16 g_att[(size_t)TTOK * 128];   // attn out (windowed, bf16)
__device__ float         g_xres[(size_t)TTOK * 128];  // x + proj (natural, fp32)
__device__ __nv_bfloat16 g_mlp[(size_t)TTOK * 512];   // gelu(fc1) (bf16)
__device__ __nv_bfloat16 g_wq[384 * 128];
__device__ __nv_bfloat16 g_wp[128 * 128];
__device__ __nv_bfloat16 g_w1[512 * 128];
__device__ __nv_bfloat16 g_w2[128 * 512];

__device__ __forceinline__ uint32_t smem_u32(const void* p) {
    return (uint32_t)__cvta_generic_to_shared(p);
}
__device__ __forceinline__ float warp_sum(float v) {
#pragma unroll
    for (int o = 16; o; o >>= 1) v += __shfl_xor_sync(0xffffffffu, v, o);
    return v;
}
__device__ __forceinline__ void cp16(uint32_t dst, const void* src) {
    asm volatile("cp.async.cg.shared.global [%0], [%1], 16;" :: "r"(dst), "l"(src));
}
__device__ __forceinline__ void cp_commit() {
    asm volatile("cp.async.commit_group;" ::: "memory");
}
template <int N>
__device__ __forceinline__ void cp_wait() {
    asm volatile("cp.async.wait_group %0;" :: "n"(N) : "memory");
}
__device__ __forceinline__ void ldm_x4(uint32_t* r, uint32_t addr) {
    asm volatile("ldmatrix.sync.aligned.m8n8.x4.shared.b16 {%0,%1,%2,%3}, [%4];"
                 : "=r"(r[0]), "=r"(r[1]), "=r"(r[2]), "=r"(r[3]) : "r"(addr));
}
__device__ __forceinline__ void ldm_x4_t(uint32_t* r, uint32_t addr) {
    asm volatile("ldmatrix.sync.aligned.m8n8.x4.trans.shared.b16 {%0,%1,%2,%3}, [%4];"
                 : "=r"(r[0]), "=r"(r[1]), "=r"(r[2]), "=r"(r[3]) : "r"(addr));
}
__device__ __forceinline__ void mma16816(float* c, const uint32_t* a, const uint32_t* b) {
    asm volatile(
        "mma.sync.aligned.m16n8k16.row.col.f32.bf16.bf16.f32 "
        "{%0,%1,%2,%3}, {%4,%5,%6,%7}, {%8,%9}, {%0,%1,%2,%3};"
        : "+f"(c[0]), "+f"(c[1]), "+f"(c[2]), "+f"(c[3])
        : "r"(a[0]), "r"(a[1]), "r"(a[2]), "r"(a[3]), "r"(b[0]), "r"(b[1]));
}
__device__ __forceinline__ uint32_t packbf2(float a, float b) {
    __nv_bfloat162 h = __floats2bfloat162_rn(a, b);
    return *(uint32_t*)&h;
}

// ---------------- fp32 -> bf16 weight conversion (all 4 in one launch) -----
__global__ void f2bf_all(const float* __restrict__ s0, __nv_bfloat16* __restrict__ d0, int n0,
                         const float* __restrict__ s1, __nv_bfloat16* __restrict__ d1, int n1,
                         const float* __restrict__ s2, __nv_bfloat16* __restrict__ d2, int n2,
                         const float* __restrict__ s3, __nv_bfloat16* __restrict__ d3, int n3) {
    int i = (blockIdx.x * blockDim.x + threadIdx.x) * 4;
    const float* s; __nv_bfloat16* d;
    if (i < n0) { s = s0 + i; d = d0 + i; }
    else if ((i -= n0) < n1) { s = s1 + i; d = d1 + i; }
    else if ((i -= n1) < n2) { s = s2 + i; d = d2 + i; }
    else if ((i -= n2) < n3) { s = s3 + i; d = d3 + i; }
    else return;
    float4 v = *(const float4*)s;
    __nv_bfloat162* dp = (__nv_bfloat162*)d;
    dp[0] = __floats2bfloat162_rn(v.x, v.y);
    dp[1] = __floats2bfloat162_rn(v.z, v.w);
}

// ---------------- LayerNorm (warp/token), bf16 out; fuses roll(-3,-3) +
// window partition into the source index. -----------------------------------
__global__ void ln1_kernel(const float* __restrict__ x, const float* __restrict__ g,
                           const float* __restrict__ b, __nv_bfloat16* __restrict__ out) {
    int gt = blockIdx.x * blockDim.x + threadIdx.x;
    int tok = gt >> 5, lane = gt & 31;
    if (tok >= TTOK) return;
    int win = tok / 49, n = tok - win * 49;
    int bb = win >> 6, wrem = win & 63;
    int ny = n / 7, nx = n - ny * 7;
    int gh = (wrem >> 3) * 7 + ny;
    int gw = (wrem & 7) * 7 + nx;
    int sh = gh + 3; if (sh >= 56) sh -= 56;
    int sw = gw + 3; if (sw >= 56) sw -= 56;
    size_t src = (size_t)bb * 3136 + sh * 56 + sw;
    float4 v = ((const float4*)(x + src * 128))[lane];
    float mu = warp_sum(v.x + v.y + v.z + v.w) * (1.0f / 128.0f);
    float dx = v.x - mu, dy = v.y - mu, dz = v.z - mu, dw = v.w - mu;
    float var = warp_sum(dx * dx + dy * dy + dz * dz + dw * dw) * (1.0f / 128.0f);
    float inv = rsqrtf(var + 1e-5f);
    float4 gg = ((const float4*)g)[lane];
    float4 bv = ((const float4*)b)[lane];
    __nv_bfloat162* op = (__nv_bfloat162*)(out + (size_t)tok * 128);
    op[lane * 2]     = __floats2bfloat162_rn(dx * inv * gg.x + bv.x, dy * inv * gg.y + bv.y);
    op[lane * 2 + 1] = __floats2bfloat162_rn(dz * inv * gg.z + bv.z, dw * inv * gg.w + bv.w);
}

// natural-order output row -> windowed-order attention row
__device__ __forceinline__ size_t proj_gather(size_t m) {
    int bb = (int)(m / 3136);
    int r  = (int)(m - (size_t)bb * 3136);
    int h = r / 56, w = r - h * 56;
    int gh = h + 53; if (gh >= 56) gh -= 56;
    int gw = w + 53; if (gw >= 56) gw -= 56;
    int win = bb * 64 + (gh / 7) * 8 + (gw / 7);
    int n = (gh % 7) * 7 + (gw % 7);
    return (size_t)win * 49 + n;
}

// ---------------- bf16 HMMA GEMM, 3-stage cp.async pipeline ----------------
// C[M,N] = A[M,K] @ W[N,K]^T. BM=BN=128, BK=32, 8 warps (4Mx2N), warp 32x64.
// One __syncthreads per K-chunk; prefetch distance 2, up to 2 loads in flight.
// AMODE: 0 = direct rows; 1 = proj_gather rows.
// EPI: 0 = bias -> bf16 ; 1 = bias + exact GELU -> bf16 ;
//      2 = bias + residual -> fp32 Cout, then LN2 -> bf16 xwout (needs N=128);
//      3 = bias + residual -> fp32 Cout.
#define SSTR 40
#define STAGE_B (128 * SSTR * 2 * 2)   // A+B per stage = 20480 bytes
#define GEMM_SMEM (3 * STAGE_B)        // 61440 bytes

template <int AMODE, int EPI>
__global__ void __launch_bounds__(256, 2)
hgemm3(const __nv_bfloat16* __restrict__ A, const __nv_bfloat16* __restrict__ W,
       const float* __restrict__ bias, const float* __restrict__ res,
       const float* __restrict__ ln_g, const float* __restrict__ ln_b,
       void* __restrict__ Cout, __nv_bfloat16* __restrict__ xwout,
       int M, int N, int K) {
    extern __shared__ char sh[];
    uint32_t sbase = smem_u32(sh);
    int t = threadIdx.x;
    int wid = t >> 5, lane = t & 31;
    int bm = blockIdx.y << 7, bn = blockIdx.x << 7;
    int wm = (wid & 3) * 32;
    int wn = (wid >> 2) * 64;

    int lrow = t >> 1;
    int half = t & 1;
    size_t ar = (size_t)(bm + lrow);
    if (AMODE == 1) ar = proj_gather(ar);
    const __nv_bfloat16* Ap = A + ar * (size_t)K + half * 16;
    const __nv_bfloat16* Wp = W + (size_t)(bn + lrow) * K + half * 16;
    uint32_t sA = sbase + lrow * (SSTR * 2) + half * 32;
    uint32_t sB = sA + 128 * SSTR * 2;

    int nk = K >> 5;
    // prologue: chunks 0,1 into stages 0,1
    {
        cp16(sA, Ap); cp16(sA + 16, Ap + 8);
        cp16(sB, Wp); cp16(sB + 16, Wp + 8);
        cp_commit();
        cp16(sA + STAGE_B, Ap + 32); cp16(sA + STAGE_B + 16, Ap + 40);
        cp16(sB + STAGE_B, Wp + 32); cp16(sB + STAGE_B + 16, Wp + 40);
        cp_commit();
    }

    float acc[2][8][4];
#pragma unroll
    for (int i = 0; i < 2; i++)
#pragma unroll
        for (int j = 0; j < 8; j++)
#pragma unroll
            for (int q = 0; q < 4; q++) acc[i][j][q] = 0.0f;

    uint32_t a_addr0 = sbase + (wm + (lane & 15)) * (SSTR * 2) + (((lane >> 4) << 3) << 1);
    uint32_t b_addr0 = sbase + 128 * SSTR * 2 +
                       (wn + (lane & 7) + ((lane >> 4) << 3)) * (SSTR * 2) +
                       ((((lane >> 3) & 1) << 3) << 1);

    int st = 0;        // stage of chunk c
    int pst = 2;       // stage of chunk c+2
    for (int c = 0; c < nk; c++) {
        cp_wait<1>();
        __syncthreads();
        if (c + 2 < nk) {   // prefetch chunk c+2 into stage consumed at c-1
            uint32_t so = pst * STAGE_B;
            const __nv_bfloat16* ap = Ap + (c + 2) * 32;
            const __nv_bfloat16* wp = Wp + (c + 2) * 32;
            cp16(sA + so, ap); cp16(sA + so + 16, ap + 8);
            cp16(sB + so, wp); cp16(sB + so + 16, wp + 8);
        }
        cp_commit();        // always commit (empty group keeps wait math uniform)
        uint32_t soff = st * STAGE_B;
#pragma unroll
        for (int kk = 0; kk < 2; kk++) {
            uint32_t af[2][4];
#pragma unroll
            for (int mt = 0; mt < 2; mt++)
                ldm_x4(af[mt], a_addr0 + soff + mt * 16 * (SSTR * 2) + kk * 32);
            uint32_t bfr[4][4];
#pragma unroll
            for (int bt = 0; bt < 4; bt++)
                ldm_x4(bfr[bt], b_addr0 + soff + bt * 16 * (SSTR * 2) + kk * 32);
#pragma unroll
            for (int mt = 0; mt < 2; mt++)
#pragma unroll
                for (int nt = 0; nt < 8; nt++)
                    mma16816(acc[mt][nt], af[mt], &bfr[nt >> 1][(nt & 1) * 2]);
        }
        if (++st == 3) st = 0;
        if (++pst == 3) pst = 0;
    }

    int r0 = lane >> 2;
    int c0 = (lane & 3) * 2;
    if (EPI == 0 || EPI == 1) {
#pragma unroll
        for (int mt = 0; mt < 2; mt++)
#pragma unroll
            for (int hf = 0; hf < 2; hf++) {
                int row = bm + wm + mt * 16 + r0 + hf * 8;
#pragma unroll
                for (int nt = 0; nt < 8; nt++) {
                    int col = bn + wn + nt * 8 + c0;
                    float v0 = acc[mt][nt][hf * 2 + 0] + bias[col];
                    float v1 = acc[mt][nt][hf * 2 + 1] + bias[col + 1];
                    if (EPI == 1) {
                        v0 = 0.5f * v0 * (1.0f + erff(v0 * 0.70710678118654752f));
                        v1 = 0.5f * v1 * (1.0f + erff(v1 * 0.70710678118654752f));
                    }
                    *(__nv_bfloat162*)((__nv_bfloat16*)Cout + (size_t)row * N + col) =
                        __floats2bfloat162_rn(v0, v1);
                }
            }
    } else if (EPI == 3) {
#pragma unroll
        for (int mt = 0; mt < 2; mt++)
#pragma unroll
            for (int hf = 0; hf < 2; hf++) {
                int row = bm + wm + mt * 16 + r0 + hf * 8;
#pragma unroll
                for (int nt = 0; nt < 8; nt++) {
                    int col = bn + wn + nt * 8 + c0;
                    float v0 = acc[mt][nt][hf * 2 + 0] + bias[col];
                    float v1 = acc[mt][nt][hf * 2 + 1] + bias[col + 1];
                    const float2 rv = *(const float2*)(res + (size_t)row * N + col);
                    *(float2*)((float*)Cout + (size_t)row * N + col) =
                        make_float2(v0 + rv.x, v1 + rv.y);
                }
            }
    } else {
        // EPI==2: bias + residual -> fp32 xres, then fused LN2 -> bf16 xwout
        float rsum[2][2], rsq[2][2];
#pragma unroll
        for (int mt = 0; mt < 2; mt++)
#pragma unroll
            for (int hf = 0; hf < 2; hf++) {
                rsum[mt][hf] = 0.0f; rsq[mt][hf] = 0.0f;
                int row = bm + wm + mt * 16 + r0 + hf * 8;
                float* xr = (float*)Cout + (size_t)row * 128;
                const float* rr = res + (size_t)row * 128;
#pragma unroll
                for (int nt = 0; nt < 8; nt++) {
                    int col = wn + nt * 8 + c0;
                    float2 rv = *(const float2*)(rr + col);
                    float v0 = acc[mt][nt][hf * 2 + 0] + bias[col] + rv.x;
                    float v1 = acc[mt][nt][hf * 2 + 1] + bias[col + 1] + rv.y;
                    *(float2*)(xr + col) = make_float2(v0, v1);
                    rsum[mt][hf] += v0 + v1;
                    rsq[mt][hf]  += v0 * v0 + v1 * v1;
                }
                rsum[mt][hf] += __shfl_xor_sync(0xffffffffu, rsum[mt][hf], 1);
                rsq[mt][hf]  += __shfl_xor_sync(0xffffffffu, rsq[mt][hf], 1);
                rsum[mt][hf] += __shfl_xor_sync(0xffffffffu, rsum[mt][hf], 2);
                rsq[mt][hf]  += __shfl_xor_sync(0xffffffffu, rsq[mt][hf], 2);
            }
        __syncthreads();                   // pipeline buffers now reusable
        float2* scr = (float2*)sh;         // [128][2] (sum, sumsq)
        if ((lane & 3) == 0) {
#pragma unroll
            for (int mt = 0; mt < 2; mt++)
#pragma unroll
                for (int hf = 0; hf < 2; hf++) {
                    int rl = wm + mt * 16 + r0 + hf * 8;
                    scr[rl * 2 + (wid >> 2)] = make_float2(rsum[mt][hf], rsq[mt][hf]);
                }
        }
        __syncthreads();
#pragma unroll
        for (int mt = 0; mt < 2; mt++)
#pragma unroll
            for (int hf = 0; hf < 2; hf++) {
                int rl = wm + mt * 16 + r0 + hf * 8;
                float2 s0 = scr[rl * 2], s1 = scr[rl * 2 + 1];
                float mu = (s0.x + s1.x) * (1.0f / 128.0f);
                float inv = rsqrtf((s0.y + s1.y) * (1.0f / 128.0f) - mu * mu + 1e-5f);
                int row = bm + rl;
                const float* xr = (const float*)Cout + (size_t)row * 128;
                __nv_bfloat16* xo = xwout + (size_t)row * 128;
#pragma unroll
                for (int nt = 0; nt < 8; nt++) {
                    int col = wn + nt * 8 + c0;
                    float2 v = *(const float2*)(xr + col);
                    float2 g = *(const float2*)(ln_g + col);
                    float2 b = *(const float2*)(ln_b + col);
                    *(__nv_bfloat162*)(xo + col) = __floats2bfloat162_rn(
                        (v.x - mu) * inv * g.x + b.x, (v.y - mu) * inv * g.y + b.y);
                }
            }
    }
}

// ---------------- Windowed attention: HMMA, one block per window -----------
#define ASTR 136
#define ATTN_SMEM (192 * ASTR * 2 + 676 * 4 + 64 * 4)

__global__ void __launch_bounds__(256)
attn_kernel(const __nv_bfloat16* __restrict__ qkv, const float* __restrict__ rpb,
            __nv_bfloat16* __restrict__ out) {
    extern __shared__ __nv_bfloat16 sm[];
    __nv_bfloat16* qs  = sm;
    __nv_bfloat16* ksm = sm + 64 * ASTR;
    __nv_bfloat16* vsm = sm + 128 * ASTR;
    float* rps4 = (float*)(sm + 192 * ASTR);
    int* regid  = (int*)(rps4 + 676);

    int win = blockIdx.x;
    int t = threadIdx.x;
    int lane = t & 31, wid = t >> 5;
    int head = wid >> 1;
    int ms = (wid & 1) * 32;

    int wrem = win & 63;
    int wh = wrem >> 3, ww = wrem & 7;
    if (t < 49) {
        int y = (t * 2341) >> 14, xx = t - y * 7;
        int gh = wh * 7 + y, gw = ww * 7 + xx;
        int rh = gh < 49 ? 0 : (gh < 53 ? 1 : 2);
        int rw = gw < 49 ? 0 : (gw < 53 ? 1 : 2);
        regid[t] = rh * 3 + rw;
    }
    for (int i = t; i < 676; i += 256) {
        int h = i / 169, r = i - h * 169;
        rps4[h * 169 + r] = rpb[r * 4 + h];
    }
    size_t base = (size_t)win * 49 * 384;
    for (int idx = t; idx < 2352; idx += 256) {
        int nn = idx / 48, c = idx - nn * 48;
        uint4 v = *(const uint4*)(qkv + base + nn * 384 + c * 8);
        int sec = c >> 4, col = (c & 15) * 8;
        __nv_bfloat16* dst = (sec == 0) ? qs : (sec == 1) ? ksm : vsm;
        *(uint4*)&dst[nn * ASTR + col] = v;
    }
    uint4 z = make_uint4(0, 0, 0, 0);
    for (int idx = t; idx < 720; idx += 256) {
        int pr = idx / 48, c = idx - pr * 48;
        int rr = 49 + pr;
        int sec = c >> 4, col = (c & 15) * 8;
        __nv_bfloat16* dst = (sec == 0) ? qs : (sec == 1) ? ksm : vsm;
        *(uint4*)&dst[rr * ASTR + col] = z;
    }
    __syncthreads();

    float sc[2][7][4];
#pragma unroll
    for (int i = 0; i < 2; i++)
#pragma unroll
        for (int j = 0; j < 7; j++)
#pragma unroll
            for (int q = 0; q < 4; q++) sc[i][j][q] = 0.0f;

    uint32_t a_base = smem_u32(&qs[(ms + (lane & 15)) * ASTR + head * 32 + ((lane >> 4) << 3)]);
    uint32_t b_base = smem_u32(&ksm[((lane & 7) + ((lane >> 4) << 3)) * ASTR + head * 32 +
                                    (((lane >> 3) & 1) << 3)]);
#pragma unroll
    for (int kk = 0; kk < 2; kk++) {
        uint32_t af[2][4];
#pragma unroll
        for (int mt = 0; mt < 2; mt++)
            ldm_x4(af[mt], a_base + (mt * 16 * ASTR + kk * 16) * 2);
        uint32_t bfr[4][4];
#pragma unroll
        for (int bt = 0; bt < 4; bt++)
            ldm_x4(bfr[bt], b_base + (bt * 16 * ASTR + kk * 16) * 2);
#pragma unroll
        for (int mt = 0; mt < 2; mt++)
#pragma unroll
            for (int nt = 0; nt < 7; nt++)
                mma16816(sc[mt][nt], af[mt], &bfr[nt >> 1][(nt & 1) * 2]);
    }

    const float SCALE = 0.17677669529663687f;
    int rY[2][2], rX[2][2], rR[2][2]; bool rV[2][2];
#pragma unroll
    for (int mt = 0; mt < 2; mt++)
#pragma unroll
        for (int rh = 0; rh < 2; rh++) {
            int r = ms + mt * 16 + (lane >> 2) + rh * 8;
            bool v = r < 49;
            rV[mt][rh] = v;
            int rc = v ? r : 0;
            rY[mt][rh] = (rc * 2341) >> 14;
            rX[mt][rh] = rc - rY[mt][rh] * 7;
            rR[mt][rh] = regid[rc];
        }
#pragma unroll
    for (int nt = 0; nt < 7; nt++) {
#pragma unroll
        for (int e = 0; e < 2; e++) {
            int m = nt * 8 + (lane & 3) * 2 + e;
            bool mv = m < 49;
            int mc = mv ? m : 0;
            int y2 = (mc * 2341) >> 14, x2 = mc - y2 * 7;
            int rm = regid[mc];
#pragma unroll
            for (int mt = 0; mt < 2; mt++)
#pragma unroll
                for (int rh = 0; rh < 2; rh++) {
                    float s = sc[mt][nt][rh * 2 + e] * SCALE;
                    if (mv && rV[mt][rh]) {
                        s += rps4[head * 169 + (rY[mt][rh] - y2 + 6) * 13 +
                                  (rX[mt][rh] - x2 + 6)];
                        if (rR[mt][rh] != rm) s -= 100.0f;
                    } else {
                        s = -1e30f;
                    }
                    sc[mt][nt][rh * 2 + e] = s;
                }
        }
    }

    float rinv[2][2];
#pragma unroll
    for (int mt = 0; mt < 2; mt++)
#pragma unroll
        for (int rh = 0; rh < 2; rh++) {
            float mx = -1e30f;
#pragma unroll
            for (int nt = 0; nt < 7; nt++)
                mx = fmaxf(mx, fmaxf(sc[mt][nt][rh * 2], sc[mt][nt][rh * 2 + 1]));
            mx = fmaxf(mx, __shfl_xor_sync(0xffffffffu, mx, 1));
            mx = fmaxf(mx, __shfl_xor_sync(0xffffffffu, mx, 2));
            float sum = 0.0f;
#pragma unroll
            for (int nt = 0; nt < 7; nt++) {
                float e0 = __expf(sc[mt][nt][rh * 2] - mx);
                float e1 = __expf(sc[mt][nt][rh * 2 + 1] - mx);
                sc[mt][nt][rh * 2] = e0;
                sc[mt][nt][rh * 2 + 1] = e1;
                sum += e0 + e1;
            }
            sum += __shfl_xor_sync(0xffffffffu, sum, 1);
            sum += __shfl_xor_sync(0xffffffffu, sum, 2);
            rinv[mt][rh] = rV[mt][rh] ? (1.0f / sum) : 0.0f;
        }

    float oc[2][4][4];
#pragma unroll
    for (int i = 0; i < 2; i++)
#pragma unroll
        for (int j = 0; j < 4; j++)
#pragma unroll
            for (int q = 0; q < 4; q++) oc[i][j][q] = 0.0f;

    uint32_t vb = smem_u32(&vsm[(lane & 15) * ASTR + head * 32 + ((lane >> 4) << 3)]);
#pragma unroll
    for (int ks = 0; ks < 4; ks++) {
        uint32_t bv[2][4];
        ldm_x4_t(bv[0], vb + (ks * 16 * ASTR) * 2);
        ldm_x4_t(bv[1], vb + (ks * 16 * ASTR + 16) * 2);
#pragma unroll
        for (int mt = 0; mt < 2; mt++) {
            float il = rinv[mt][0], ih = rinv[mt][1];
            int n0 = 2 * ks, n1 = 2 * ks + 1;
            uint32_t a[4];
            a[0] = packbf2(sc[mt][n0][0] * il, sc[mt][n0][1] * il);
            a[1] = packbf2(sc[mt][n0][2] * ih, sc[mt][n0][3] * ih);
            if (n1 < 7) {
                a[2] = packbf2(sc[mt][n1][0] * il, sc[mt][n1][1] * il);
                a[3] = packbf2(sc[mt][n1][2] * ih, sc[mt][n1][3] * ih);
            } else {
                a[2] = 0u; a[3] = 0u;
            }
#pragma unroll
            for (int dt = 0; dt < 4; dt++)
                mma16816(oc[mt][dt], a, &bv[dt >> 1][(dt & 1) * 2]);
        }
    }

    size_t ob = (size_t)win * 49 * 128 + head * 32;
#pragma unroll
    for (int mt = 0; mt < 2; mt++)
#pragma unroll
        for (int rh = 0; rh < 2; rh++) {
            int r = ms + mt * 16 + (lane >> 2) + rh * 8;
            if (r < 49) {
#pragma unroll
                for (int dt = 0; dt < 4; dt++) {
                    int d = dt * 8 + (lane & 3) * 2;
                    __nv_bfloat162 o2 = __floats2bfloat162_rn(oc[mt][dt][rh * 2],
                                                              oc[mt][dt][rh * 2 + 1]);
                    *(__nv_bfloat162*)(out + ob + (size_t)r * 128 + d) = o2;
                }
            }
        }
}

// ---------------- launch ---------------------------------------------------
extern "C" void kernel_launch(void* const* d_in, const int* in_sizes, int n_in,
                              void* d_out, int out_size) {
    const float* x      = (const float*)d_in[0];
    const float* ln1_g  = (const float*)d_in[1];
    const float* ln1_b  = (const float*)d_in[2];
    const float* qkv_w  = (const float*)d_in[3];
    const float* qkv_b  = (const float*)d_in[4];
    const float* rpb    = (const float*)d_in[5];
    const float* proj_w = (const float*)d_in[6];
    const float* proj_b = (const float*)d_in[7];
    const float* ln2_g  = (const float*)d_in[8];
    const float* ln2_b  = (const float*)d_in[9];
    const float* fc1_w  = (const float*)d_in[10];
    const float* fc1_b  = (const float*)d_in[11];
    const float* fc2_w  = (const float*)d_in[12];
    const float* fc2_b  = (const float*)d_in[13];
    float* out = (float*)d_out;

    void* p;
    cudaGetSymbolAddress(&p, g_xw);   __nv_bfloat16* xw   = (__nv_bfloat16*)p;
    cudaGetSymbolAddress(&p, g_qkv);  __nv_bfloat16* qkvb = (__nv_bfloat16*)p;
    cudaGetSymbolAddress(&p, g_att);  __nv_bfloat16* att  = (__nv_bfloat16*)p;
    cudaGetSymbolAddress(&p, g_xres); float*         xres = (float*)p;
    cudaGetSymbolAddress(&p, g_mlp);  __nv_bfloat16* mlp  = (__nv_bfloat16*)p;
    cudaGetSymbolAddress(&p, g_wq);   __nv_bfloat16* wq = (__nv_bfloat16*)p;
    cudaGetSymbolAddress(&p, g_wp);   __nv_bfloat16* wp = (__nv_bfloat16*)p;
    cudaGetSymbolAddress(&p, g_w1);   __nv_bfloat16* w1 = (__nv_bfloat16*)p;
    cudaGetSymbolAddress(&p, g_w2);   __nv_bfloat16* w2 = (__nv_bfloat16*)p;

    cudaFuncSetAttribute(attn_kernel, cudaFuncAttributeMaxDynamicSharedMemorySize, ATTN_SMEM);
    cudaFuncSetAttribute(hgemm3<0, 0>, cudaFuncAttributeMaxDynamicSharedMemorySize, GEMM_SMEM);
    cudaFuncSetAttribute(hgemm3<1, 2>, cudaFuncAttributeMaxDynamicSharedMemorySize, GEMM_SMEM);
    cudaFuncSetAttribute(hgemm3<0, 1>, cudaFuncAttributeMaxDynamicSharedMemorySize, GEMM_SMEM);
    cudaFuncSetAttribute(hgemm3<0, 3>, cudaFuncAttributeMaxDynamicSharedMemorySize, GEMM_SMEM);

    // weight conversion (bf16), single launch
    f2bf_all<<<192, 256>>>(qkv_w, wq, 384 * 128, proj_w, wp, 128 * 128,
                           fc1_w, w1, 512 * 128, fc2_w, w2, 128 * 512);

    const int LN_BLOCKS = (TTOK * 32) / 256;  // 25088

    // 1. LN1 + shift + window partition (bf16 out)
    ln1_kernel<<<LN_BLOCKS, 256>>>(x, ln1_g, ln1_b, xw);
    // 2. QKV projection (3-stage pipelined HMMA)
    hgemm3<0, 0><<<dim3(3, 1568), 256, GEMM_SMEM>>>(
        xw, wq, qkv_b, nullptr, nullptr, nullptr, qkvb, nullptr, TTOK, 384, 128);
    // 3. Windowed attention
    attn_kernel<<<4096, 256, ATTN_SMEM>>>(qkvb, rpb, att);
    // 4. proj + window-reverse gather + residual -> xres, fused LN2 -> xw
    hgemm3<1, 2><<<dim3(1, 1568), 256, GEMM_SMEM>>>(
        att, wp, proj_b, x, ln2_g, ln2_b, xres, xw, TTOK, 128, 128);
    // 5. fc1 + exact GELU
    hgemm3<0, 1><<<dim3(4, 1568), 256, GEMM_SMEM>>>(
        xw, w1, fc1_b, nullptr, nullptr, nullptr, mlp, nullptr, TTOK, 512, 128);
    // 6. fc2 + residual -> output (fp32)
    hgemm3<0, 3><<<dim3(1, 1568), 256, GEMM_SMEM>>>(
        mlp, w2, fc2_b, xres, nullptr, nullptr, out, nullptr, TTOK, 128, 512);
}

// round 17
// speedup vs baseline: 1.1938x; 1.0289x over previous
#include <cuda_runtime.h>
#include <cuda_bf16.h>
#include <math.h>
#include <stdint.h>

#define TTOK 200704          // B*H*W = 64*56*56 tokens
// C=128, QKD=128, HID=512, NH=4, HD=32, WS=7, N=49, NW=64

// ---------------- scratch (device globals; no allocation allowed) ----------
__device__ __nv_bfloat16 g_xw [(size_t)TTOK * 128];   // LN output (bf16)
__device__ __nv_bfloat16 g_qkv[(size_t)TTOK * 384];   // qkv (windowed, bf16)
__device__ __nv_bfloat16 g_att[(size_t)TTOK * 128];   // attn out (windowed, bf16)
__device__ float         g_xres[(size_t)TTOK * 128];  // x + proj (natural, fp32)
__device__ __nv_bfloat16 g_wq[384 * 128];
__device__ __nv_bfloat16 g_wp[128 * 128];
__device__ __nv_bfloat16 g_w1[512 * 128];
__device__ __nv_bfloat16 g_w2[128 * 512];
__device__ __nv_bfloat16 g_btab[64 * 4 * 64 * 64];    // [wrem][head][r][m] bias+mask

__device__ __forceinline__ uint32_t smem_u32(const void* p) {
    return (uint32_t)__cvta_generic_to_shared(p);
}
__device__ __forceinline__ float warp_sum(float v) {
#pragma unroll
    for (int o = 16; o; o >>= 1) v += __shfl_xor_sync(0xffffffffu, v, o);
    return v;
}
__device__ __forceinline__ void cp16(uint32_t dst, const void* src) {
    asm volatile("cp.async.cg.shared.global [%0], [%1], 16;" :: "r"(dst), "l"(src));
}
__device__ __forceinline__ void cp_commit() {
    asm volatile("cp.async.commit_group;" ::: "memory");
}
template <int N>
__device__ __forceinline__ void cp_wait() {
    asm volatile("cp.async.wait_group %0;" :: "n"(N) : "memory");
}
__device__ __forceinline__ void ldm_x4(uint32_t* r, uint32_t addr) {
    asm volatile("ldmatrix.sync.aligned.m8n8.x4.shared.b16 {%0,%1,%2,%3}, [%4];"
                 : "=r"(r[0]), "=r"(r[1]), "=r"(r[2]), "=r"(r[3]) : "r"(addr));
}
__device__ __forceinline__ void ldm_x4_t(uint32_t* r, uint32_t addr) {
    asm volatile("ldmatrix.sync.aligned.m8n8.x4.trans.shared.b16 {%0,%1,%2,%3}, [%4];"
                 : "=r"(r[0]), "=r"(r[1]), "=r"(r[2]), "=r"(r[3]) : "r"(addr));
}
__device__ __forceinline__ void mma16816(float* c, const uint32_t* a, const uint32_t* b) {
    asm volatile(
        "mma.sync.aligned.m16n8k16.row.col.f32.bf16.bf16.f32 "
        "{%0,%1,%2,%3}, {%4,%5,%6,%7}, {%8,%9}, {%0,%1,%2,%3};"
        : "+f"(c[0]), "+f"(c[1]), "+f"(c[2]), "+f"(c[3])
        : "r"(a[0]), "r"(a[1]), "r"(a[2]), "r"(a[3]), "r"(b[0]), "r"(b[1]));
}
__device__ __forceinline__ uint32_t packbf2(float a, float b) {
    __nv_bfloat162 h = __floats2bfloat162_rn(a, b);
    return *(uint32_t*)&h;
}

// ---------------- precompute rel-pos bias + shift mask table ---------------
// btab[wrem][head][r][m] = rpb + (-100 if cross-region) ; -1e30 for pad rows/cols
__global__ void fill_btab(const float* __restrict__ rpb, __nv_bfloat16* __restrict__ tab) {
    int i = blockIdx.x * 256 + threadIdx.x;   // bf16 PAIR index
    if (i >= 64 * 4 * 64 * 32) return;
    int m2 = i & 31;
    int r  = (i >> 5) & 63;
    int head = (i >> 11) & 3;
    int wrem = i >> 13;
    int wh = wrem >> 3, ww = wrem & 7;
    float v[2];
    int y1 = 0, x1 = 0, reg1 = 0;
    bool rvalid = r < 49;
    if (rvalid) {
        y1 = r / 7; x1 = r - y1 * 7;
        int gh = wh * 7 + y1, gw = ww * 7 + x1;
        reg1 = (gh < 49 ? 0 : (gh < 53 ? 1 : 2)) * 3 + (gw < 49 ? 0 : (gw < 53 ? 1 : 2));
    }
#pragma unroll
    for (int e = 0; e < 2; e++) {
        int m = m2 * 2 + e;
        if (!rvalid || m >= 49) { v[e] = -1e30f; continue; }
        int y2 = m / 7, x2 = m - y2 * 7;
        int gh = wh * 7 + y2, gw = ww * 7 + x2;
        int reg2 = (gh < 49 ? 0 : (gh < 53 ? 1 : 2)) * 3 + (gw < 49 ? 0 : (gw < 53 ? 1 : 2));
        float s = rpb[((y1 - y2 + 6) * 13 + (x1 - x2 + 6)) * 4 + head];
        if (reg1 != reg2) s -= 100.0f;
        v[e] = s;
    }
    __nv_bfloat162 h2 = __floats2bfloat162_rn(v[0], v[1]);
    *(__nv_bfloat162*)(tab + (size_t)i * 2) = h2;
}

// ---------------- fp32 -> bf16 weight conversion (all 4 in one launch) -----
__global__ void f2bf_all(const float* __restrict__ s0, __nv_bfloat16* __restrict__ d0, int n0,
                         const float* __restrict__ s1, __nv_bfloat16* __restrict__ d1, int n1,
                         const float* __restrict__ s2, __nv_bfloat16* __restrict__ d2, int n2,
                         const float* __restrict__ s3, __nv_bfloat16* __restrict__ d3, int n3) {
    int i = (blockIdx.x * blockDim.x + threadIdx.x) * 4;
    const float* s; __nv_bfloat16* d;
    if (i < n0) { s = s0 + i; d = d0 + i; }
    else if ((i -= n0) < n1) { s = s1 + i; d = d1 + i; }
    else if ((i -= n1) < n2) { s = s2 + i; d = d2 + i; }
    else if ((i -= n2) < n3) { s = s3 + i; d = d3 + i; }
    else return;
    float4 v = *(const float4*)s;
    __nv_bfloat162* dp = (__nv_bfloat162*)d;
    dp[0] = __floats2bfloat162_rn(v.x, v.y);
    dp[1] = __floats2bfloat162_rn(v.z, v.w);
}

// ---------------- LayerNorm (warp/token), bf16 out; fuses roll(-3,-3) +
// window partition into the source index. -----------------------------------
__global__ void ln1_kernel(const float* __restrict__ x, const float* __restrict__ g,
                           const float* __restrict__ b, __nv_bfloat16* __restrict__ out) {
    int gt = blockIdx.x * blockDim.x + threadIdx.x;
    int tok = gt >> 5, lane = gt & 31;
    if (tok >= TTOK) return;
    int win = tok / 49, n = tok - win * 49;
    int bb = win >> 6, wrem = win & 63;
    int ny = n / 7, nx = n - ny * 7;
    int gh = (wrem >> 3) * 7 + ny;
    int gw = (wrem & 7) * 7 + nx;
    int sh = gh + 3; if (sh >= 56) sh -= 56;
    int sw = gw + 3; if (sw >= 56) sw -= 56;
    size_t src = (size_t)bb * 3136 + sh * 56 + sw;
    float4 v = ((const float4*)(x + src * 128))[lane];
    float mu = warp_sum(v.x + v.y + v.z + v.w) * (1.0f / 128.0f);
    float dx = v.x - mu, dy = v.y - mu, dz = v.z - mu, dw = v.w - mu;
    float var = warp_sum(dx * dx + dy * dy + dz * dz + dw * dw) * (1.0f / 128.0f);
    float inv = rsqrtf(var + 1e-5f);
    float4 gg = ((const float4*)g)[lane];
    float4 bv = ((const float4*)b)[lane];
    __nv_bfloat162* op = (__nv_bfloat162*)(out + (size_t)tok * 128);
    op[lane * 2]     = __floats2bfloat162_rn(dx * inv * gg.x + bv.x, dy * inv * gg.y + bv.y);
    op[lane * 2 + 1] = __floats2bfloat162_rn(dz * inv * gg.z + bv.z, dw * inv * gg.w + bv.w);
}

// natural-order output row -> windowed-order attention row
__device__ __forceinline__ size_t proj_gather(size_t m) {
    int bb = (int)(m / 3136);
    int r  = (int)(m - (size_t)bb * 3136);
    int h = r / 56, w = r - h * 56;
    int gh = h + 53; if (gh >= 56) gh -= 56;
    int gw = w + 53; if (gw >= 56) gw -= 56;
    int win = bb * 64 + (gh / 7) * 8 + (gw / 7);
    int n = (gh % 7) * 7 + (gw % 7);
    return (size_t)win * 49 + n;
}

// ---------------- bf16 HMMA GEMM, 3-stage cp.async pipeline ----------------
// AMODE: 0 = direct rows; 1 = proj_gather rows.
// EPI: 0 = bias -> bf16 ;
//      2 = bias + residual -> fp32 Cout, then LN2 -> bf16 xwout (needs N=128)
#define SSTR 40
#define STAGE_B (128 * SSTR * 2 * 2)   // A+B per stage = 20480 bytes
#define GEMM_SMEM (3 * STAGE_B)        // 61440 bytes

template <int AMODE, int EPI>
__global__ void __launch_bounds__(256, 2)
hgemm3(const __nv_bfloat16* __restrict__ A, const __nv_bfloat16* __restrict__ W,
       const float* __restrict__ bias, const float* __restrict__ res,
       const float* __restrict__ ln_g, const float* __restrict__ ln_b,
       void* __restrict__ Cout, __nv_bfloat16* __restrict__ xwout,
       int M, int N, int K) {
    extern __shared__ char sh[];
    uint32_t sbase = smem_u32(sh);
    int t = threadIdx.x;
    int wid = t >> 5, lane = t & 31;
    int bm = blockIdx.y << 7, bn = blockIdx.x << 7;
    int wm = (wid & 3) * 32;
    int wn = (wid >> 2) * 64;

    int lrow = t >> 1;
    int half = t & 1;
    size_t ar = (size_t)(bm + lrow);
    if (AMODE == 1) ar = proj_gather(ar);
    const __nv_bfloat16* Ap = A + ar * (size_t)K + half * 16;
    const __nv_bfloat16* Wp = W + (size_t)(bn + lrow) * K + half * 16;
    uint32_t sA = sbase + lrow * (SSTR * 2) + half * 32;
    uint32_t sB = sA + 128 * SSTR * 2;

    int nk = K >> 5;
    {
        cp16(sA, Ap); cp16(sA + 16, Ap + 8);
        cp16(sB, Wp); cp16(sB + 16, Wp + 8);
        cp_commit();
        cp16(sA + STAGE_B, Ap + 32); cp16(sA + STAGE_B + 16, Ap + 40);
        cp16(sB + STAGE_B, Wp + 32); cp16(sB + STAGE_B + 16, Wp + 40);
        cp_commit();
    }

    float acc[2][8][4];
#pragma unroll
    for (int i = 0; i < 2; i++)
#pragma unroll
        for (int j = 0; j < 8; j++)
#pragma unroll
            for (int q = 0; q < 4; q++) acc[i][j][q] = 0.0f;

    uint32_t a_addr0 = sbase + (wm + (lane & 15)) * (SSTR * 2) + (((lane >> 4) << 3) << 1);
    uint32_t b_addr0 = sbase + 128 * SSTR * 2 +
                       (wn + (lane & 7) + ((lane >> 4) << 3)) * (SSTR * 2) +
                       ((((lane >> 3) & 1) << 3) << 1);

    int st = 0;
    int pst = 2;
    for (int c = 0; c < nk; c++) {
        cp_wait<1>();
        __syncthreads();
        if (c + 2 < nk) {
            uint32_t so = pst * STAGE_B;
            const __nv_bfloat16* ap = Ap + (c + 2) * 32;
            const __nv_bfloat16* wp = Wp + (c + 2) * 32;
            cp16(sA + so, ap); cp16(sA + so + 16, ap + 8);
            cp16(sB + so, wp); cp16(sB + so + 16, wp + 8);
        }
        cp_commit();
        uint32_t soff = st * STAGE_B;
#pragma unroll
        for (int kk = 0; kk < 2; kk++) {
            uint32_t af[2][4];
#pragma unroll
            for (int mt = 0; mt < 2; mt++)
                ldm_x4(af[mt], a_addr0 + soff + mt * 16 * (SSTR * 2) + kk * 32);
            uint32_t bfr[4][4];
#pragma unroll
            for (int bt = 0; bt < 4; bt++)
                ldm_x4(bfr[bt], b_addr0 + soff + bt * 16 * (SSTR * 2) + kk * 32);
#pragma unroll
            for (int mt = 0; mt < 2; mt++)
#pragma unroll
                for (int nt = 0; nt < 8; nt++)
                    mma16816(acc[mt][nt], af[mt], &bfr[nt >> 1][(nt & 1) * 2]);
        }
        if (++st == 3) st = 0;
        if (++pst == 3) pst = 0;
    }

    int r0 = lane >> 2;
    int c0 = (lane & 3) * 2;
    if (EPI == 0) {
#pragma unroll
        for (int mt = 0; mt < 2; mt++)
#pragma unroll
            for (int hf = 0; hf < 2; hf++) {
                int row = bm + wm + mt * 16 + r0 + hf * 8;
#pragma unroll
                for (int nt = 0; nt < 8; nt++) {
                    int col = bn + wn + nt * 8 + c0;
                    float v0 = acc[mt][nt][hf * 2 + 0] + bias[col];
                    float v1 = acc[mt][nt][hf * 2 + 1] + bias[col + 1];
                    *(__nv_bfloat162*)((__nv_bfloat16*)Cout + (size_t)row * N + col) =
                        __floats2bfloat162_rn(v0, v1);
                }
            }
    } else {
        // EPI==2: bias + residual -> fp32 xres, then fused LN2 -> bf16 xwout
        float rsum[2][2], rsq[2][2];
#pragma unroll
        for (int mt = 0; mt < 2; mt++)
#pragma unroll
            for (int hf = 0; hf < 2; hf++) {
                rsum[mt][hf] = 0.0f; rsq[mt][hf] = 0.0f;
                int row = bm + wm + mt * 16 + r0 + hf * 8;
                float* xr = (float*)Cout + (size_t)row * 128;
                const float* rr = res + (size_t)row * 128;
#pragma unroll
                for (int nt = 0; nt < 8; nt++) {
                    int col = wn + nt * 8 + c0;
                    float2 rv = *(const float2*)(rr + col);
                    float v0 = acc[mt][nt][hf * 2 + 0] + bias[col] + rv.x;
                    float v1 = acc[mt][nt][hf * 2 + 1] + bias[col + 1] + rv.y;
                    *(float2*)(xr + col) = make_float2(v0, v1);
                    rsum[mt][hf] += v0 + v1;
                    rsq[mt][hf]  += v0 * v0 + v1 * v1;
                }
                rsum[mt][hf] += __shfl_xor_sync(0xffffffffu, rsum[mt][hf], 1);
                rsq[mt][hf]  += __shfl_xor_sync(0xffffffffu, rsq[mt][hf], 1);
                rsum[mt][hf] += __shfl_xor_sync(0xffffffffu, rsum[mt][hf], 2);
                rsq[mt][hf]  += __shfl_xor_sync(0xffffffffu, rsq[mt][hf], 2);
            }
        __syncthreads();
        float2* scr = (float2*)sh;
        if ((lane & 3) == 0) {
#pragma unroll
            for (int mt = 0; mt < 2; mt++)
#pragma unroll
                for (int hf = 0; hf < 2; hf++) {
                    int rl = wm + mt * 16 + r0 + hf * 8;
                    scr[rl * 2 + (wid >> 2)] = make_float2(rsum[mt][hf], rsq[mt][hf]);
                }
        }
        __syncthreads();
#pragma unroll
        for (int mt = 0; mt < 2; mt++)
#pragma unroll
            for (int hf = 0; hf < 2; hf++) {
                int rl = wm + mt * 16 + r0 + hf * 8;
                float2 s0 = scr[rl * 2], s1 = scr[rl * 2 + 1];
                float mu = (s0.x + s1.x) * (1.0f / 128.0f);
                float inv = rsqrtf((s0.y + s1.y) * (1.0f / 128.0f) - mu * mu + 1e-5f);
                int row = bm + rl;
                const float* xr = (const float*)Cout + (size_t)row * 128;
                __nv_bfloat16* xo = xwout + (size_t)row * 128;
#pragma unroll
                for (int nt = 0; nt < 8; nt++) {
                    int col = wn + nt * 8 + c0;
                    float2 v = *(const float2*)(xr + col);
                    float2 g = *(const float2*)(ln_g + col);
                    float2 b = *(const float2*)(ln_b + col);
                    *(__nv_bfloat162*)(xo + col) = __floats2bfloat162_rn(
                        (v.x - mu) * inv * g.x + b.x, (v.y - mu) * inv * g.y + b.y);
                }
            }
    }
}

// ---------------- fused MLP: out = gelu(xw@W1^T+b1)@W2^T + b2 + xres -------
// One 128-token tile per CTA. h (128x512 bf16) lives entirely in smem.
#define MLP_OFF_A 0
#define MLP_OFF_H 34816
#define MLP_OFF_W 167936
#define MLP_SMEM  220160

__global__ void __launch_bounds__(256, 1)
fc_fused(const __nv_bfloat16* __restrict__ xw, const __nv_bfloat16* __restrict__ w1,
         const float* __restrict__ b1, const __nv_bfloat16* __restrict__ w2,
         const float* __restrict__ b2, const float* __restrict__ xres,
         float* __restrict__ out) {
    extern __shared__ char sh[];
    uint32_t sbase = smem_u32(sh);
    const uint32_t offA = sbase + MLP_OFF_A;
    const uint32_t offH = sbase + MLP_OFF_H;
    const uint32_t offW = sbase + MLP_OFF_W;
    int t = threadIdx.x;
    int wid = t >> 5, lane = t & 31;
    int bm = blockIdx.y << 7;
    int r0 = lane >> 2, c0 = (lane & 3) * 2;
    int wm = (wid & 3) * 32;

    int wrow = t >> 2, wp4 = t & 3;
    // ---- prologue: A tile + W1 chunks 0,1
    {
        int lrow = t >> 1, half = t & 1;
        const __nv_bfloat16* ap = xw + (size_t)(bm + lrow) * 128 + half * 64;
        uint32_t dA = offA + lrow * 272 + half * 128;
#pragma unroll
        for (int i = 0; i < 8; i++) cp16(dA + i * 16, ap + i * 8);
        const __nv_bfloat16* s0 = w1 + (size_t)wrow * 128 + wp4 * 32;
        uint32_t d0 = offW + wrow * 272 + wp4 * 64;
#pragma unroll
        for (int i = 0; i < 4; i++) cp16(d0 + i * 16, s0 + i * 8);
        cp_commit();
        const __nv_bfloat16* s1 = w1 + (size_t)(64 + wrow) * 128 + wp4 * 32;
        uint32_t d1 = offW + 17408 + wrow * 272 + wp4 * 64;
#pragma unroll
        for (int i = 0; i < 4; i++) cp16(d1 + i * 16, s1 + i * 8);
        cp_commit();
    }

    int wn1 = (wid >> 2) * 32;
    uint32_t a_ad  = offA + (wm + (lane & 15)) * 272 + (((lane >> 4) << 3) << 1);
    uint32_t b1_ad = offW + (wn1 + (lane & 7) + ((lane >> 4) << 3)) * 272 +
                     ((((lane >> 3) & 1) << 3) << 1);

    // ---- phase 1: h = gelu(A @ W1^T + b1), 8 chunks of 64 N-rows
    for (int j = 0; j < 8; j++) {
        cp_wait<1>();
        __syncthreads();
        if (j + 2 < 8) {
            const __nv_bfloat16* s = w1 + (size_t)((j + 2) * 64 + wrow) * 128 + wp4 * 32;
            uint32_t d = offW + ((j + 2) % 3) * 17408 + wrow * 272 + wp4 * 64;
#pragma unroll
            for (int i = 0; i < 4; i++) cp16(d + i * 16, s + i * 8);
        }
        cp_commit();
        uint32_t bb = b1_ad + (j % 3) * 17408;
        float acc[2][4][4];
#pragma unroll
        for (int a = 0; a < 2; a++)
#pragma unroll
            for (int b = 0; b < 4; b++)
#pragma unroll
                for (int q = 0; q < 4; q++) acc[a][b][q] = 0.0f;
#pragma unroll
        for (int kk = 0; kk < 8; kk++) {
            uint32_t af[2][4];
            ldm_x4(af[0], a_ad + kk * 32);
            ldm_x4(af[1], a_ad + 16 * 272 + kk * 32);
            uint32_t bfr[2][4];
            ldm_x4(bfr[0], bb + kk * 32);
            ldm_x4(bfr[1], bb + 16 * 272 + kk * 32);
#pragma unroll
            for (int mt = 0; mt < 2; mt++)
#pragma unroll
                for (int nt = 0; nt < 4; nt++)
                    mma16816(acc[mt][nt], af[mt], &bfr[nt >> 1][(nt & 1) * 2]);
        }
        // epilogue -> h smem (bias + exact GELU, bf16)
#pragma unroll
        for (int mt = 0; mt < 2; mt++)
#pragma unroll
            for (int hf = 0; hf < 2; hf++) {
                int row = wm + mt * 16 + r0 + hf * 8;
#pragma unroll
                for (int nt = 0; nt < 4; nt++) {
                    int col = wn1 + nt * 8 + c0;
                    float v0 = acc[mt][nt][hf * 2 + 0] + b1[j * 64 + col];
                    float v1 = acc[mt][nt][hf * 2 + 1] + b1[j * 64 + col + 1];
                    v0 = 0.5f * v0 * (1.0f + erff(v0 * 0.70710678118654752f));
                    v1 = 0.5f * v1 * (1.0f + erff(v1 * 0.70710678118654752f));
                    *(uint32_t*)(sh + MLP_OFF_H + row * 1040 + (j * 64 + col) * 2) =
                        packbf2(v0, v1);
                }
            }
    }
    cp_wait<0>();
    __syncthreads();

    // ---- phase 2: out = h @ W2^T + b2 + xres, K=512 in 16 chunks of 32
    {
        int l2 = t >> 1, h2 = t & 1;
        const __nv_bfloat16* s0 = w2 + (size_t)l2 * 512 + h2 * 16;
        uint32_t d0 = offW + l2 * 80 + h2 * 32;
        cp16(d0, s0); cp16(d0 + 16, s0 + 8);
        cp_commit();
        const __nv_bfloat16* s1 = s0 + 32;
        uint32_t d1 = offW + 10240 + l2 * 80 + h2 * 32;
        cp16(d1, s1); cp16(d1 + 16, s1 + 8);
        cp_commit();
    }
    int wn2 = (wid >> 2) * 64;
    uint32_t ha_ad = offH + (wm + (lane & 15)) * 1040 + (((lane >> 4) << 3) << 1);
    uint32_t b2_ad = offW + (wn2 + (lane & 7) + ((lane >> 4) << 3)) * 80 +
                     ((((lane >> 3) & 1) << 3) << 1);

    float acc2[2][8][4];
#pragma unroll
    for (int a = 0; a < 2; a++)
#pragma unroll
        for (int b = 0; b < 8; b++)
#pragma unroll
            for (int q = 0; q < 4; q++) acc2[a][b][q] = 0.0f;

    for (int c = 0; c < 16; c++) {
        cp_wait<1>();
        __syncthreads();
        if (c + 2 < 16) {
            int l2 = t >> 1, h2 = t & 1;
            const __nv_bfloat16* s = w2 + (size_t)l2 * 512 + (c + 2) * 32 + h2 * 16;
            uint32_t d = offW + ((c + 2) % 3) * 10240 + l2 * 80 + h2 * 32;
            cp16(d, s); cp16(d + 16, s + 8);
        }
        cp_commit();
        uint32_t soA = ha_ad + c * 64;
        uint32_t soB = b2_ad + (c % 3) * 10240;
#pragma unroll
        for (int kk = 0; kk < 2; kk++) {
            uint32_t af[2][4];
            ldm_x4(af[0], soA + kk * 32);
            ldm_x4(af[1], soA + 16 * 1040 + kk * 32);
            uint32_t bfr[4][4];
#pragma unroll
            for (int bt = 0; bt < 4; bt++)
                ldm_x4(bfr[bt], soB + bt * 16 * 80 + kk * 32);
#pragma unroll
            for (int mt = 0; mt < 2; mt++)
#pragma unroll
                for (int nt = 0; nt < 8; nt++)
                    mma16816(acc2[mt][nt], af[mt], &bfr[nt >> 1][(nt & 1) * 2]);
        }
    }

    // ---- epilogue: + b2 + xres -> fp32 out
#pragma unroll
    for (int mt = 0; mt < 2; mt++)
#pragma unroll
        for (int hf = 0; hf < 2; hf++) {
            int row = bm + wm + mt * 16 + r0 + hf * 8;
#pragma unroll
            for (int nt = 0; nt < 8; nt++) {
                int col = wn2 + nt * 8 + c0;
                float v0 = acc2[mt][nt][hf * 2 + 0] + b2[col];
                float v1 = acc2[mt][nt][hf * 2 + 1] + b2[col + 1];
                const float2 rv = *(const float2*)(xres + (size_t)row * 128 + col);
                *(float2*)(out + (size_t)row * 128 + col) =
                    make_float2(v0 + rv.x, v1 + rv.y);
            }
        }
}

// ---------------- Windowed attention: HMMA, one block per window -----------
#define ASTR 136
#define ATTN_SMEM (192 * ASTR * 2)

__global__ void __launch_bounds__(256)
attn_kernel(const __nv_bfloat16* __restrict__ qkv, const __nv_bfloat16* __restrict__ btab,
            __nv_bfloat16* __restrict__ out) {
    extern __shared__ __nv_bfloat16 sm[];
    __nv_bfloat16* qs  = sm;
    __nv_bfloat16* ksm = sm + 64 * ASTR;
    __nv_bfloat16* vsm = sm + 128 * ASTR;

    int win = blockIdx.x;
    int t = threadIdx.x;
    int lane = t & 31, wid = t >> 5;
    int head = wid >> 1;
    int ms = (wid & 1) * 32;
    int r0 = lane >> 2, c0 = (lane & 3) * 2;

    size_t base = (size_t)win * 49 * 384;
    for (int idx = t; idx < 2352; idx += 256) {
        int nn = idx / 48, c = idx - nn * 48;
        uint4 v = *(const uint4*)(qkv + base + nn * 384 + c * 8);
        int sec = c >> 4, col = (c & 15) * 8;
        __nv_bfloat16* dst = (sec == 0) ? qs : (sec == 1) ? ksm : vsm;
        *(uint4*)&dst[nn * ASTR + col] = v;
    }
    uint4 z = make_uint4(0, 0, 0, 0);
    for (int idx = t; idx < 720; idx += 256) {
        int pr = idx / 48, c = idx - pr * 48;
        int rr = 49 + pr;
        int sec = c >> 4, col = (c & 15) * 8;
        __nv_bfloat16* dst = (sec == 0) ? qs : (sec == 1) ? ksm : vsm;
        *(uint4*)&dst[rr * ASTR + col] = z;
    }
    __syncthreads();

    float sc[2][7][4];
#pragma unroll
    for (int i = 0; i < 2; i++)
#pragma unroll
        for (int j = 0; j < 7; j++)
#pragma unroll
            for (int q = 0; q < 4; q++) sc[i][j][q] = 0.0f;

    uint32_t a_base = smem_u32(&qs[(ms + (lane & 15)) * ASTR + head * 32 + ((lane >> 4) << 3)]);
    uint32_t b_base = smem_u32(&ksm[((lane & 7) + ((lane >> 4) << 3)) * ASTR + head * 32 +
                                    (((lane >> 3) & 1) << 3)]);
#pragma unroll
    for (int kk = 0; kk < 2; kk++) {
        uint32_t af[2][4];
#pragma unroll
        for (int mt = 0; mt < 2; mt++)
            ldm_x4(af[mt], a_base + (mt * 16 * ASTR + kk * 16) * 2);
        uint32_t bfr[4][4];
#pragma unroll
        for (int bt = 0; bt < 4; bt++)
            ldm_x4(bfr[bt], b_base + (bt * 16 * ASTR + kk * 16) * 2);
#pragma unroll
        for (int mt = 0; mt < 2; mt++)
#pragma unroll
            for (int nt = 0; nt < 7; nt++)
                mma16816(sc[mt][nt], af[mt], &bfr[nt >> 1][(nt & 1) * 2]);
    }

    // ---- scale + precomputed (bias+mask) table, in-register ---------------
    const float SCALE = 0.17677669529663687f;
    bool rV[2][2];
    const __nv_bfloat16* tb = btab + ((size_t)((win & 63) * 4 + head) << 12);
#pragma unroll
    for (int mt = 0; mt < 2; mt++)
#pragma unroll
        for (int rh = 0; rh < 2; rh++) {
            int r = ms + mt * 16 + r0 + rh * 8;
            rV[mt][rh] = (r < 49);
            const __nv_bfloat16* rowp = tb + r * 64 + c0;
#pragma unroll
            for (int nt = 0; nt < 7; nt++) {
                uint32_t u = *(const uint32_t*)(rowp + nt * 8);
                float2 bv = __bfloat1622float2(*(__nv_bfloat162*)&u);
                sc[mt][nt][rh * 2]     = fmaf(sc[mt][nt][rh * 2],     SCALE, bv.x);
                sc[mt][nt][rh * 2 + 1] = fmaf(sc[mt][nt][rh * 2 + 1], SCALE, bv.y);
            }
        }

    // ---- register softmax -------------------------------------------------
    float rinv[2][2];
#pragma unroll
    for (int mt = 0; mt < 2; mt++)
#pragma unroll
        for (int rh = 0; rh < 2; rh++) {
            float mx = -1e30f;
#pragma unroll
            for (int nt = 0; nt < 7; nt++)
                mx = fmaxf(mx, fmaxf(sc[mt][nt][rh * 2], sc[mt][nt][rh * 2 + 1]));
            mx = fmaxf(mx, __shfl_xor_sync(0xffffffffu, mx, 1));
            mx = fmaxf(mx, __shfl_xor_sync(0xffffffffu, mx, 2));
            float sum = 0.0f;
#pragma unroll
            for (int nt = 0; nt < 7; nt++) {
                float e0 = __expf(sc[mt][nt][rh * 2] - mx);
                float e1 = __expf(sc[mt][nt][rh * 2 + 1] - mx);
                sc[mt][nt][rh * 2] = e0;
                sc[mt][nt][rh * 2 + 1] = e1;
                sum += e0 + e1;
            }
            sum += __shfl_xor_sync(0xffffffffu, sum, 1);
            sum += __shfl_xor_sync(0xffffffffu, sum, 2);
            rinv[mt][rh] = rV[mt][rh] ? (1.0f / sum) : 0.0f;
        }

    float oc[2][4][4];
#pragma unroll
    for (int i = 0; i < 2; i++)
#pragma unroll
        for (int j = 0; j < 4; j++)
#pragma unroll
            for (int q = 0; q < 4; q++) oc[i][j][q] = 0.0f;

    uint32_t vb = smem_u32(&vsm[(lane & 15) * ASTR + head * 32 + ((lane >> 4) << 3)]);
#pragma unroll
    for (int ks = 0; ks < 4; ks++) {
        uint32_t bv[2][4];
        ldm_x4_t(bv[0], vb + (ks * 16 * ASTR) * 2);
        ldm_x4_t(bv[1], vb + (ks * 16 * ASTR + 16) * 2);
#pragma unroll
        for (int mt = 0; mt < 2; mt++) {
            float il = rinv[mt][0], ih = rinv[mt][1];
            int n0 = 2 * ks, n1 = 2 * ks + 1;
            uint32_t a[4];
            a[0] = packbf2(sc[mt][n0][0] * il, sc[mt][n0][1] * il);
            a[1] = packbf2(sc[mt][n0][2] * ih, sc[mt][n0][3] * ih);
            if (n1 < 7) {
                a[2] = packbf2(sc[mt][n1][0] * il, sc[mt][n1][1] * il);
                a[3] = packbf2(sc[mt][n1][2] * ih, sc[mt][n1][3] * ih);
            } else {
                a[2] = 0u; a[3] = 0u;
            }
#pragma unroll
            for (int dt = 0; dt < 4; dt++)
                mma16816(oc[mt][dt], a, &bv[dt >> 1][(dt & 1) * 2]);
        }
    }

    size_t ob = (size_t)win * 49 * 128 + head * 32;
#pragma unroll
    for (int mt = 0; mt < 2; mt++)
#pragma unroll
        for (int rh = 0; rh < 2; rh++) {
            int r = ms + mt * 16 + r0 + rh * 8;
            if (r < 49) {
#pragma unroll
                for (int dt = 0; dt < 4; dt++) {
                    int d = dt * 8 + c0;
                    __nv_bfloat162 o2 = __floats2bfloat162_rn(oc[mt][dt][rh * 2],
                                                              oc[mt][dt][rh * 2 + 1]);
                    *(__nv_bfloat162*)(out + ob + (size_t)r * 128 + d) = o2;
                }
            }
        }
}

// ---------------- launch ---------------------------------------------------
extern "C" void kernel_launch(void* const* d_in, const int* in_sizes, int n_in,
                              void* d_out, int out_size) {
    const float* x      = (const float*)d_in[0];
    const float* ln1_g  = (const float*)d_in[1];
    const float* ln1_b  = (const float*)d_in[2];
    const float* qkv_w  = (const float*)d_in[3];
    const float* qkv_b  = (const float*)d_in[4];
    const float* rpb    = (const float*)d_in[5];
    const float* proj_w = (const float*)d_in[6];
    const float* proj_b = (const float*)d_in[7];
    const float* ln2_g  = (const float*)d_in[8];
    const float* ln2_b  = (const float*)d_in[9];
    const float* fc1_w  = (const float*)d_in[10];
    const float* fc1_b  = (const float*)d_in[11];
    const float* fc2_w  = (const float*)d_in[12];
    const float* fc2_b  = (const float*)d_in[13];
    float* out = (float*)d_out;

    void* p;
    cudaGetSymbolAddress(&p, g_xw);   __nv_bfloat16* xw   = (__nv_bfloat16*)p;
    cudaGetSymbolAddress(&p, g_qkv);  __nv_bfloat16* qkvb = (__nv_bfloat16*)p;
    cudaGetSymbolAddress(&p, g_att);  __nv_bfloat16* att  = (__nv_bfloat16*)p;
    cudaGetSymbolAddress(&p, g_xres); float*         xres = (float*)p;
    cudaGetSymbolAddress(&p, g_wq);   __nv_bfloat16* wq = (__nv_bfloat16*)p;
    cudaGetSymbolAddress(&p, g_wp);   __nv_bfloat16* wp = (__nv_bfloat16*)p;
    cudaGetSymbolAddress(&p, g_w1);   __nv_bfloat16* w1 = (__nv_bfloat16*)p;
    cudaGetSymbolAddress(&p, g_w2);   __nv_bfloat16* w2 = (__nv_bfloat16*)p;
    cudaGetSymbolAddress(&p, g_btab); __nv_bfloat16* btab = (__nv_bfloat16*)p;

    cudaFuncSetAttribute(attn_kernel, cudaFuncAttributeMaxDynamicSharedMemorySize, ATTN_SMEM);
    cudaFuncSetAttribute(hgemm3<0, 0>, cudaFuncAttributeMaxDynamicSharedMemorySize, GEMM_SMEM);
    cudaFuncSetAttribute(hgemm3<1, 2>, cudaFuncAttributeMaxDynamicSharedMemorySize, GEMM_SMEM);
    cudaFuncSetAttribute(fc_fused, cudaFuncAttributeMaxDynamicSharedMemorySize, MLP_SMEM);

    // precompute bias+mask table and bf16 weights
    fill_btab<<<2048, 256>>>(rpb, btab);
    f2bf_all<<<192, 256>>>(qkv_w, wq, 384 * 128, proj_w, wp, 128 * 128,
                           fc1_w, w1, 512 * 128, fc2_w, w2, 128 * 512);

    const int LN_BLOCKS = (TTOK * 32) / 256;  // 25088

    // 1. LN1 + shift + window partition (bf16 out)
    ln1_kernel<<<LN_BLOCKS, 256>>>(x, ln1_g, ln1_b, xw);
    // 2. QKV projection (3-stage pipelined HMMA)
    hgemm3<0, 0><<<dim3(3, 1568), 256, GEMM_SMEM>>>(
        xw, wq, qkv_b, nullptr, nullptr, nullptr, qkvb, nullptr, TTOK, 384, 128);
    // 3. Windowed attention (table-based bias+mask)
    attn_kernel<<<4096, 256, ATTN_SMEM>>>(qkvb, btab, att);
    // 4. proj + window-reverse gather + residual -> xres, fused LN2 -> xw
    hgemm3<1, 2><<<dim3(1, 1568), 256, GEMM_SMEM>>>(
        att, wp, proj_b, x, ln2_g, ln2_b, xres, xw, TTOK, 128, 128);
    // 5. fused MLP: fc1 + GELU + fc2 + residual -> output (fp32)
    fc_fused<<<dim3(1, 1568), 256, MLP_SMEM>>>(xw, w1, fc1_b, w2, fc2_b, xres, out);
}